// round 1
// baseline (speedup 1.0000x reference)
#include <cuda_runtime.h>

#define NHEADS 16
#define DHEAD  64
#define BATCH  4
#define SEQ    2048
#define DIMM   1024
#define BHTOT  (BATCH * NHEADS)

// Scratch for projected Q/K/V in [B,H,N,Dh] layout (no cudaMalloc allowed).
__device__ float g_q[BHTOT * SEQ * DHEAD];
__device__ float g_k[BHTOT * SEQ * DHEAD];
__device__ float g_v[BHTOT * SEQ * DHEAD];

// ---------------------------------------------------------------------------
// Fused QKV projection: C[8192,1024] = X @ W + b, scattered into [B,H,N,Dh].
// blockIdx.z selects q/k/v. 64x64 tile per block, 4x4 per thread, K-tile 32.
// ---------------------------------------------------------------------------
__global__ __launch_bounds__(256) void qkv_kernel(
    const float* __restrict__ x,
    const float* __restrict__ Wq, const float* __restrict__ bq,
    const float* __restrict__ Wk, const float* __restrict__ bk,
    const float* __restrict__ Wv, const float* __restrict__ bv)
{
    __shared__ float Xs[32][68];  // transposed: Xs[k][m]
    __shared__ float Ws[32][68];  // natural:    Ws[k][n]

    const int z = blockIdx.z;
    const float* W    = (z == 0) ? Wq : ((z == 1) ? Wk : Wv);
    const float* bias = (z == 0) ? bq : ((z == 1) ? bk : bv);
    float* outp       = (z == 0) ? g_q : ((z == 1) ? g_k : g_v);

    const int tid = threadIdx.x;
    const int tx = tid & 15;   // col group
    const int ty = tid >> 4;   // row group
    const int m0 = blockIdx.y * 64;
    const int n0 = blockIdx.x * 64;

    float acc[4][4] = {};

    for (int k0 = 0; k0 < DIMM; k0 += 32) {
        // Load X tile (64 rows x 32 k) transposed into Xs.
        {
            int idx = tid;
            #pragma unroll
            for (int it = 0; it < 2; it++, idx += 256) {
                int r = idx >> 3, k4 = idx & 7;
                float4 v = *(const float4*)(x + (size_t)(m0 + r) * DIMM + k0 + k4 * 4);
                Xs[k4 * 4 + 0][r] = v.x;
                Xs[k4 * 4 + 1][r] = v.y;
                Xs[k4 * 4 + 2][r] = v.z;
                Xs[k4 * 4 + 3][r] = v.w;
            }
        }
        // Load W tile (32 k x 64 cols) natural into Ws.
        {
            int idx = tid;
            #pragma unroll
            for (int it = 0; it < 2; it++, idx += 256) {
                int k = idx >> 4, c4 = idx & 15;
                float4 v = *(const float4*)(W + (size_t)(k0 + k) * DIMM + n0 + c4 * 4);
                *(float4*)&Ws[k][c4 * 4] = v;
            }
        }
        __syncthreads();

        #pragma unroll
        for (int kk = 0; kk < 32; kk++) {
            float4 a = *(const float4*)&Xs[kk][ty * 4];
            float4 b = *(const float4*)&Ws[kk][tx * 4];
            float av[4] = {a.x, a.y, a.z, a.w};
            float bv[4] = {b.x, b.y, b.z, b.w};
            #pragma unroll
            for (int i = 0; i < 4; i++)
                #pragma unroll
                for (int j = 0; j < 4; j++)
                    acc[i][j] = fmaf(av[i], bv[j], acc[i][j]);
        }
        __syncthreads();
    }

    // Epilogue: add bias, scatter into [B,H,N,Dh].
    #pragma unroll
    for (int i = 0; i < 4; i++) {
        int m = m0 + ty * 4 + i;
        int b = m >> 11;          // /2048
        int n = m & 2047;
        #pragma unroll
        for (int j = 0; j < 4; j++) {
            int col = n0 + tx * 4 + j;
            int h = col >> 6;
            int d = col & 63;
            outp[(((size_t)(b * NHEADS + h)) * SEQ + n) * DHEAD + d] =
                acc[i][j] + bias[col];
        }
    }
}

// ---------------------------------------------------------------------------
// Flash attention: per (bh, q-tile of 64 rows). Bc = 32 kv cols per step.
// Online softmax, everything fp32. 256 threads, 4 rows x (2 S-cols / 4 O-cols)
// per thread.
// ---------------------------------------------------------------------------
__global__ __launch_bounds__(256) void attn_kernel(float* __restrict__ out)
{
    __shared__ float Qt[64][68];  // Qt[d][r], pre-scaled
    __shared__ float Kt[64][34];  // Kt[d][c]
    __shared__ float Vs[32][68];  // Vs[c][d]
    __shared__ float Pt[32][68];  // Pt[c][r]

    const int tid = threadIdx.x;
    const int tx = tid & 15;
    const int ty = tid >> 4;
    const int bh  = blockIdx.y;
    const int qr0 = blockIdx.x * 64;

    const float* qp = g_q + (size_t)bh * SEQ * DHEAD;
    const float* kp = g_k + (size_t)bh * SEQ * DHEAD;
    const float* vp = g_v + (size_t)bh * SEQ * DHEAD;

    const float scale = 0.125f;  // 1/sqrt(64)

    // Load Q tile (64 x 64), transpose, fold in softmax scale.
    for (int idx = tid; idx < 64 * 16; idx += 256) {
        int r = idx >> 4, d4 = idx & 15;
        float4 v = *(const float4*)(qp + (size_t)(qr0 + r) * DHEAD + d4 * 4);
        Qt[d4 * 4 + 0][r] = v.x * scale;
        Qt[d4 * 4 + 1][r] = v.y * scale;
        Qt[d4 * 4 + 2][r] = v.z * scale;
        Qt[d4 * 4 + 3][r] = v.w * scale;
    }

    float m_i[4], l_i[4], o[4][4] = {};
    #pragma unroll
    for (int i = 0; i < 4; i++) { m_i[i] = -1e30f; l_i[i] = 0.0f; }

    __syncthreads();

    for (int kc0 = 0; kc0 < SEQ; kc0 += 32) {
        // Load K tile (32 x 64) transposed and V tile (32 x 64) natural.
        for (int idx = tid; idx < 32 * 16; idx += 256) {
            int c = idx >> 4, d4 = idx & 15;
            float4 kv = *(const float4*)(kp + (size_t)(kc0 + c) * DHEAD + d4 * 4);
            Kt[d4 * 4 + 0][c] = kv.x;
            Kt[d4 * 4 + 1][c] = kv.y;
            Kt[d4 * 4 + 2][c] = kv.z;
            Kt[d4 * 4 + 3][c] = kv.w;
            float4 vv = *(const float4*)(vp + (size_t)(kc0 + c) * DHEAD + d4 * 4);
            *(float4*)&Vs[c][d4 * 4] = vv;
        }
        __syncthreads();

        // S = Q * K^T for this tile: each thread 4 rows x 2 cols.
        float s[4][2] = {};
        #pragma unroll 16
        for (int d = 0; d < 64; d++) {
            float4 a = *(const float4*)&Qt[d][ty * 4];
            float b0 = Kt[d][tx * 2 + 0];
            float b1 = Kt[d][tx * 2 + 1];
            s[0][0] = fmaf(a.x, b0, s[0][0]); s[0][1] = fmaf(a.x, b1, s[0][1]);
            s[1][0] = fmaf(a.y, b0, s[1][0]); s[1][1] = fmaf(a.y, b1, s[1][1]);
            s[2][0] = fmaf(a.z, b0, s[2][0]); s[2][1] = fmaf(a.z, b1, s[2][1]);
            s[3][0] = fmaf(a.w, b0, s[3][0]); s[3][1] = fmaf(a.w, b1, s[3][1]);
        }

        // Online softmax per row (row spread over 16 tx threads, width-16 shfl).
        #pragma unroll
        for (int i = 0; i < 4; i++) {
            float mx = fmaxf(s[i][0], s[i][1]);
            #pragma unroll
            for (int off = 8; off >= 1; off >>= 1)
                mx = fmaxf(mx, __shfl_xor_sync(0xffffffffu, mx, off, 16));
            float mnew = fmaxf(m_i[i], mx);
            float alpha = __expf(m_i[i] - mnew);
            float p0 = __expf(s[i][0] - mnew);
            float p1 = __expf(s[i][1] - mnew);
            s[i][0] = p0; s[i][1] = p1;
            float rs = p0 + p1;
            #pragma unroll
            for (int off = 8; off >= 1; off >>= 1)
                rs += __shfl_xor_sync(0xffffffffu, rs, off, 16);
            l_i[i] = l_i[i] * alpha + rs;
            m_i[i] = mnew;
            o[i][0] *= alpha; o[i][1] *= alpha; o[i][2] *= alpha; o[i][3] *= alpha;
        }

        // Write P transposed for the PV matmul.
        #pragma unroll
        for (int i = 0; i < 4; i++) {
            Pt[tx * 2 + 0][ty * 4 + i] = s[i][0];
            Pt[tx * 2 + 1][ty * 4 + i] = s[i][1];
        }
        __syncthreads();

        // O += P * V : each thread 4 rows x 4 d-cols.
        #pragma unroll 8
        for (int cc = 0; cc < 32; cc++) {
            float4 a = *(const float4*)&Pt[cc][ty * 4];
            float4 b = *(const float4*)&Vs[cc][tx * 4];
            float av[4] = {a.x, a.y, a.z, a.w};
            float bv[4] = {b.x, b.y, b.z, b.w};
            #pragma unroll
            for (int i = 0; i < 4; i++)
                #pragma unroll
                for (int j = 0; j < 4; j++)
                    o[i][j] = fmaf(av[i], bv[j], o[i][j]);
        }
        __syncthreads();  // protect Kt/Vs/Pt before next tile's loads
    }

    // Normalize and write out in [B, N, D] layout.
    const int b = bh >> 4;
    const int h = bh & 15;
    #pragma unroll
    for (int i = 0; i < 4; i++) {
        int n = qr0 + ty * 4 + i;
        float inv = 1.0f / l_i[i];
        float4 res;
        res.x = o[i][0] * inv;
        res.y = o[i][1] * inv;
        res.z = o[i][2] * inv;
        res.w = o[i][3] * inv;
        *(float4*)(out + ((size_t)b * SEQ + n) * DIMM + h * DHEAD + tx * 4) = res;
    }
}

// ---------------------------------------------------------------------------
extern "C" void kernel_launch(void* const* d_in, const int* in_sizes, int n_in,
                              void* d_out, int out_size)
{
    const float* x  = (const float*)d_in[0];
    const float* Wq = (const float*)d_in[1];
    const float* bq = (const float*)d_in[2];
    const float* Wk = (const float*)d_in[3];
    const float* bk = (const float*)d_in[4];
    const float* Wv = (const float*)d_in[5];
    const float* bv = (const float*)d_in[6];
    float* out = (float*)d_out;

    dim3 g1(DIMM / 64, (BATCH * SEQ) / 64, 3);   // (16, 128, 3)
    qkv_kernel<<<g1, 256>>>(x, Wq, bq, Wk, bk, Wv, bv);

    dim3 g2(SEQ / 64, BHTOT);                    // (32, 64)
    attn_kernel<<<g2, 256>>>(out);
}

// round 2
// speedup vs baseline: 1.0007x; 1.0007x over previous
#include <cuda_runtime.h>

#define NHEADS 16
#define DHEAD  64
#define BATCH  4
#define SEQ    2048
#define DIMM   1024
#define BHTOT  (BATCH * NHEADS)

// Scratch for projected Q/K/V in [B,H,N,Dh] layout (no cudaMalloc allowed).
__device__ float g_q[BHTOT * SEQ * DHEAD];
__device__ float g_k[BHTOT * SEQ * DHEAD];
__device__ float g_v[BHTOT * SEQ * DHEAD];

// ---------------------------------------------------------------------------
// Fused QKV projection: C[8192,1024] = X @ W + b, scattered into [B,H,N,Dh].
// blockIdx.z selects q/k/v. 64x64 tile per block, 4x4 per thread, K-tile 32.
// ---------------------------------------------------------------------------
__global__ __launch_bounds__(256) void qkv_kernel(
    const float* __restrict__ x,
    const float* __restrict__ Wq, const float* __restrict__ bq,
    const float* __restrict__ Wk, const float* __restrict__ bk,
    const float* __restrict__ Wv, const float* __restrict__ bv)
{
    __shared__ float Xs[32][68];  // transposed: Xs[k][m]
    __shared__ float Ws[32][68];  // natural:    Ws[k][n]

    const int z = blockIdx.z;
    const float* W    = (z == 0) ? Wq : ((z == 1) ? Wk : Wv);
    const float* bias = (z == 0) ? bq : ((z == 1) ? bk : bv);
    float* outp       = (z == 0) ? g_q : ((z == 1) ? g_k : g_v);

    const int tid = threadIdx.x;
    const int tx = tid & 15;   // col group
    const int ty = tid >> 4;   // row group
    const int m0 = blockIdx.y * 64;
    const int n0 = blockIdx.x * 64;

    float acc[4][4] = {};

    for (int k0 = 0; k0 < DIMM; k0 += 32) {
        // Load X tile (64 rows x 32 k) transposed into Xs.
        {
            int idx = tid;
            #pragma unroll
            for (int it = 0; it < 2; it++, idx += 256) {
                int r = idx >> 3, k4 = idx & 7;
                float4 v = *(const float4*)(x + (size_t)(m0 + r) * DIMM + k0 + k4 * 4);
                Xs[k4 * 4 + 0][r] = v.x;
                Xs[k4 * 4 + 1][r] = v.y;
                Xs[k4 * 4 + 2][r] = v.z;
                Xs[k4 * 4 + 3][r] = v.w;
            }
        }
        // Load W tile (32 k x 64 cols) natural into Ws.
        {
            int idx = tid;
            #pragma unroll
            for (int it = 0; it < 2; it++, idx += 256) {
                int k = idx >> 4, c4 = idx & 15;
                float4 v = *(const float4*)(W + (size_t)(k0 + k) * DIMM + n0 + c4 * 4);
                *(float4*)&Ws[k][c4 * 4] = v;
            }
        }
        __syncthreads();

        #pragma unroll
        for (int kk = 0; kk < 32; kk++) {
            float4 a = *(const float4*)&Xs[kk][ty * 4];
            float4 b = *(const float4*)&Ws[kk][tx * 4];
            float av[4] = {a.x, a.y, a.z, a.w};
            float bv[4] = {b.x, b.y, b.z, b.w};
            #pragma unroll
            for (int i = 0; i < 4; i++)
                #pragma unroll
                for (int j = 0; j < 4; j++)
                    acc[i][j] = fmaf(av[i], bv[j], acc[i][j]);
        }
        __syncthreads();
    }

    // Epilogue: add bias, scatter into [B,H,N,Dh].
    #pragma unroll
    for (int i = 0; i < 4; i++) {
        int m = m0 + ty * 4 + i;
        int b = m >> 11;          // /2048
        int n = m & 2047;
        #pragma unroll
        for (int j = 0; j < 4; j++) {
            int col = n0 + tx * 4 + j;
            int h = col >> 6;
            int d = col & 63;
            outp[(((size_t)(b * NHEADS + h)) * SEQ + n) * DHEAD + d] =
                acc[i][j] + bias[col];
        }
    }
}

// ---------------------------------------------------------------------------
// Flash attention: per (bh, q-tile of 64 rows). Bc = 32 kv cols per step.
// Online softmax, everything fp32. 256 threads, 4 rows x (2 S-cols / 4 O-cols)
// per thread.
// ---------------------------------------------------------------------------
__global__ __launch_bounds__(256) void attn_kernel(float* __restrict__ out)
{
    __shared__ float Qt[64][68];  // Qt[d][r], pre-scaled
    __shared__ float Kt[64][34];  // Kt[d][c]
    __shared__ float Vs[32][68];  // Vs[c][d]
    __shared__ float Pt[32][68];  // Pt[c][r]

    const int tid = threadIdx.x;
    const int tx = tid & 15;
    const int ty = tid >> 4;
    const int bh  = blockIdx.y;
    const int qr0 = blockIdx.x * 64;

    const float* qp = g_q + (size_t)bh * SEQ * DHEAD;
    const float* kp = g_k + (size_t)bh * SEQ * DHEAD;
    const float* vp = g_v + (size_t)bh * SEQ * DHEAD;

    const float scale = 0.125f;  // 1/sqrt(64)

    // Load Q tile (64 x 64), transpose, fold in softmax scale.
    for (int idx = tid; idx < 64 * 16; idx += 256) {
        int r = idx >> 4, d4 = idx & 15;
        float4 v = *(const float4*)(qp + (size_t)(qr0 + r) * DHEAD + d4 * 4);
        Qt[d4 * 4 + 0][r] = v.x * scale;
        Qt[d4 * 4 + 1][r] = v.y * scale;
        Qt[d4 * 4 + 2][r] = v.z * scale;
        Qt[d4 * 4 + 3][r] = v.w * scale;
    }

    float m_i[4], l_i[4], o[4][4] = {};
    #pragma unroll
    for (int i = 0; i < 4; i++) { m_i[i] = -1e30f; l_i[i] = 0.0f; }

    __syncthreads();

    for (int kc0 = 0; kc0 < SEQ; kc0 += 32) {
        // Load K tile (32 x 64) transposed and V tile (32 x 64) natural.
        for (int idx = tid; idx < 32 * 16; idx += 256) {
            int c = idx >> 4, d4 = idx & 15;
            float4 kv = *(const float4*)(kp + (size_t)(kc0 + c) * DHEAD + d4 * 4);
            Kt[d4 * 4 + 0][c] = kv.x;
            Kt[d4 * 4 + 1][c] = kv.y;
            Kt[d4 * 4 + 2][c] = kv.z;
            Kt[d4 * 4 + 3][c] = kv.w;
            float4 vv = *(const float4*)(vp + (size_t)(kc0 + c) * DHEAD + d4 * 4);
            *(float4*)&Vs[c][d4 * 4] = vv;
        }
        __syncthreads();

        // S = Q * K^T for this tile: each thread 4 rows x 2 cols.
        float s[4][2] = {};
        #pragma unroll 16
        for (int d = 0; d < 64; d++) {
            float4 a = *(const float4*)&Qt[d][ty * 4];
            float b0 = Kt[d][tx * 2 + 0];
            float b1 = Kt[d][tx * 2 + 1];
            s[0][0] = fmaf(a.x, b0, s[0][0]); s[0][1] = fmaf(a.x, b1, s[0][1]);
            s[1][0] = fmaf(a.y, b0, s[1][0]); s[1][1] = fmaf(a.y, b1, s[1][1]);
            s[2][0] = fmaf(a.z, b0, s[2][0]); s[2][1] = fmaf(a.z, b1, s[2][1]);
            s[3][0] = fmaf(a.w, b0, s[3][0]); s[3][1] = fmaf(a.w, b1, s[3][1]);
        }

        // Online softmax per row (row spread over 16 tx threads, width-16 shfl).
        #pragma unroll
        for (int i = 0; i < 4; i++) {
            float mx = fmaxf(s[i][0], s[i][1]);
            #pragma unroll
            for (int off = 8; off >= 1; off >>= 1)
                mx = fmaxf(mx, __shfl_xor_sync(0xffffffffu, mx, off, 16));
            float mnew = fmaxf(m_i[i], mx);
            float alpha = __expf(m_i[i] - mnew);
            float p0 = __expf(s[i][0] - mnew);
            float p1 = __expf(s[i][1] - mnew);
            s[i][0] = p0; s[i][1] = p1;
            float rs = p0 + p1;
            #pragma unroll
            for (int off = 8; off >= 1; off >>= 1)
                rs += __shfl_xor_sync(0xffffffffu, rs, off, 16);
            l_i[i] = l_i[i] * alpha + rs;
            m_i[i] = mnew;
            o[i][0] *= alpha; o[i][1] *= alpha; o[i][2] *= alpha; o[i][3] *= alpha;
        }

        // Write P transposed for the PV matmul.
        #pragma unroll
        for (int i = 0; i < 4; i++) {
            Pt[tx * 2 + 0][ty * 4 + i] = s[i][0];
            Pt[tx * 2 + 1][ty * 4 + i] = s[i][1];
        }
        __syncthreads();

        // O += P * V : each thread 4 rows x 4 d-cols.
        #pragma unroll 8
        for (int cc = 0; cc < 32; cc++) {
            float4 a = *(const float4*)&Pt[cc][ty * 4];
            float4 b = *(const float4*)&Vs[cc][tx * 4];
            float av[4] = {a.x, a.y, a.z, a.w};
            float bv[4] = {b.x, b.y, b.z, b.w};
            #pragma unroll
            for (int i = 0; i < 4; i++)
                #pragma unroll
                for (int j = 0; j < 4; j++)
                    o[i][j] = fmaf(av[i], bv[j], o[i][j]);
        }
        __syncthreads();  // protect Kt/Vs/Pt before next tile's loads
    }

    // Normalize and write out in [B, N, D] layout.
    const int b = bh >> 4;
    const int h = bh & 15;
    #pragma unroll
    for (int i = 0; i < 4; i++) {
        int n = qr0 + ty * 4 + i;
        float inv = 1.0f / l_i[i];
        float4 res;
        res.x = o[i][0] * inv;
        res.y = o[i][1] * inv;
        res.z = o[i][2] * inv;
        res.w = o[i][3] * inv;
        *(float4*)(out + ((size_t)b * SEQ + n) * DIMM + h * DHEAD + tx * 4) = res;
    }
}

// ---------------------------------------------------------------------------
extern "C" void kernel_launch(void* const* d_in, const int* in_sizes, int n_in,
                              void* d_out, int out_size)
{
    const float* x  = (const float*)d_in[0];
    const float* Wq = (const float*)d_in[1];
    const float* bq = (const float*)d_in[2];
    const float* Wk = (const float*)d_in[3];
    const float* bk = (const float*)d_in[4];
    const float* Wv = (const float*)d_in[5];
    const float* bv = (const float*)d_in[6];
    float* out = (float*)d_out;

    dim3 g1(DIMM / 64, (BATCH * SEQ) / 64, 3);   // (16, 128, 3)
    qkv_kernel<<<g1, 256>>>(x, Wq, bq, Wk, bk, Wv, bv);

    dim3 g2(SEQ / 64, BHTOT);                    // (32, 64)
    attn_kernel<<<g2, 256>>>(out);
}

// round 4
// speedup vs baseline: 3.5380x; 3.5356x over previous
#include <cuda_runtime.h>

#define NHEADS 16
#define DHEAD  64
#define BATCH  4
#define SEQ    2048
#define DIMM   1024
#define BHTOT  (BATCH * NHEADS)

// Scratch for projected Q/K/V in [B,H,N,Dh] layout (no cudaMalloc allowed).
__device__ float g_q[BHTOT * SEQ * DHEAD];
__device__ float g_k[BHTOT * SEQ * DHEAD];
__device__ float g_v[BHTOT * SEQ * DHEAD];

// ---------------------------------------------------------------------------
// Helpers
// ---------------------------------------------------------------------------
__device__ __forceinline__ float f2tf32f(float f) {
    unsigned r;
    asm("cvt.rna.tf32.f32 %0, %1;" : "=r"(r) : "f"(f));
    return __uint_as_float(r);
}

__device__ __forceinline__ void mma_tf32(float* d, const unsigned* a,
                                         unsigned b0, unsigned b1) {
    asm volatile(
        "mma.sync.aligned.m16n8k8.row.col.f32.tf32.tf32.f32 "
        "{%0,%1,%2,%3}, {%4,%5,%6,%7}, {%8,%9}, {%0,%1,%2,%3};\n"
        : "+f"(d[0]), "+f"(d[1]), "+f"(d[2]), "+f"(d[3])
        : "r"(a[0]), "r"(a[1]), "r"(a[2]), "r"(a[3]), "r"(b0), "r"(b1));
}

// ---------------------------------------------------------------------------
// Fused QKV projection with TF32 tensor cores.
// C[8192,1024] = X @ W + b, scattered into [B,H,N,Dh]. blockIdx.z = q/k/v.
// Block tile 128x128, 8 warps (2m x 4n), warp tile 64x32, k-tile 32.
// ---------------------------------------------------------------------------
__global__ __launch_bounds__(256) void qkv_tc(
    const float* __restrict__ x,
    const float* __restrict__ Wq, const float* __restrict__ bq,
    const float* __restrict__ Wk, const float* __restrict__ bk,
    const float* __restrict__ Wv, const float* __restrict__ bv)
{
    __shared__ float As[128][36];   // [m][k], pad -> conflict-free frag loads
    __shared__ float Bs[32][136];   // [k][n]

    const int z = blockIdx.z;
    const float* W    = (z == 0) ? Wq : ((z == 1) ? Wk : Wv);
    const float* bias = (z == 0) ? bq : ((z == 1) ? bk : bv);
    float* outp       = (z == 0) ? g_q : ((z == 1) ? g_k : g_v);

    const int tid  = threadIdx.x;
    const int warp = tid >> 5;
    const int lane = tid & 31;
    const int g    = lane >> 2;
    const int t4   = lane & 3;
    const int wm   = warp >> 2;        // 0..1
    const int wn   = warp & 3;         // 0..3
    const int m0   = blockIdx.y * 128;
    const int n0   = blockIdx.x * 128;

    // Prefetch first k-tile (4 float4 each for A and B per thread).
    float4 aldg[4], bldg[4];
    {
        #pragma unroll
        for (int it = 0; it < 4; it++) {
            int idx = tid + it * 256;
            int m = idx >> 3, k4 = idx & 7;
            aldg[it] = *(const float4*)(x + (size_t)(m0 + m) * DIMM + k4 * 4);
            int k = idx >> 5, n4 = idx & 31;
            bldg[it] = *(const float4*)(W + (size_t)k * DIMM + n0 + n4 * 4);
        }
    }

    float acc[4][4][4] = {};

    for (int k0 = 0; k0 < DIMM; k0 += 32) {
        // Commit prefetched tile to smem (tf32-rounded).
        #pragma unroll
        for (int it = 0; it < 4; it++) {
            int idx = tid + it * 256;
            int m = idx >> 3, k4 = idx & 7;
            float4 v = aldg[it];
            As[m][k4 * 4 + 0] = f2tf32f(v.x);
            As[m][k4 * 4 + 1] = f2tf32f(v.y);
            As[m][k4 * 4 + 2] = f2tf32f(v.z);
            As[m][k4 * 4 + 3] = f2tf32f(v.w);
            int k = idx >> 5, n4 = idx & 31;
            float4 w = bldg[it];
            Bs[k][n4 * 4 + 0] = f2tf32f(w.x);
            Bs[k][n4 * 4 + 1] = f2tf32f(w.y);
            Bs[k][n4 * 4 + 2] = f2tf32f(w.z);
            Bs[k][n4 * 4 + 3] = f2tf32f(w.w);
        }
        __syncthreads();

        // Prefetch next k-tile.
        if (k0 + 32 < DIMM) {
            #pragma unroll
            for (int it = 0; it < 4; it++) {
                int idx = tid + it * 256;
                int m = idx >> 3, k4 = idx & 7;
                aldg[it] = *(const float4*)(x + (size_t)(m0 + m) * DIMM + (k0 + 32) + k4 * 4);
                int k = idx >> 5, n4 = idx & 31;
                bldg[it] = *(const float4*)(W + (size_t)(k0 + 32 + k) * DIMM + n0 + n4 * 4);
            }
        }

        #pragma unroll
        for (int s = 0; s < 4; s++) {
            unsigned a[4][4];
            #pragma unroll
            for (int mt = 0; mt < 4; mt++) {
                int row = wm * 64 + mt * 16 + g;
                int kk = s * 8 + t4;
                a[mt][0] = __float_as_uint(As[row][kk]);
                a[mt][1] = __float_as_uint(As[row + 8][kk]);
                a[mt][2] = __float_as_uint(As[row][kk + 4]);
                a[mt][3] = __float_as_uint(As[row + 8][kk + 4]);
            }
            unsigned b[4][2];
            #pragma unroll
            for (int nt = 0; nt < 4; nt++) {
                int col = wn * 32 + nt * 8 + g;
                b[nt][0] = __float_as_uint(Bs[s * 8 + t4][col]);
                b[nt][1] = __float_as_uint(Bs[s * 8 + t4 + 4][col]);
            }
            #pragma unroll
            for (int mt = 0; mt < 4; mt++)
                #pragma unroll
                for (int nt = 0; nt < 4; nt++)
                    mma_tf32(acc[mt][nt], a[mt], b[nt][0], b[nt][1]);
        }
        __syncthreads();
    }

    // Epilogue: bias add + scatter to [B,H,N,Dh].
    #pragma unroll
    for (int nt = 0; nt < 4; nt++) {
        int col = n0 + wn * 32 + nt * 8 + 2 * t4;
        float bv0 = bias[col], bv1 = bias[col + 1];
        int h = col >> 6, d = col & 63;
        #pragma unroll
        for (int mt = 0; mt < 4; mt++) {
            int row = m0 + wm * 64 + mt * 16 + g;
            int b0_ = row >> 11, n_ = row & 2047;
            float* p0 = outp + (((size_t)(b0_ * NHEADS + h)) * SEQ + n_) * DHEAD + d;
            *(float2*)p0 = make_float2(acc[mt][nt][0] + bv0, acc[mt][nt][1] + bv1);
            int row1 = row + 8;
            int b1_ = row1 >> 11, n1_ = row1 & 2047;
            float* p1 = outp + (((size_t)(b1_ * NHEADS + h)) * SEQ + n1_) * DHEAD + d;
            *(float2*)p1 = make_float2(acc[mt][nt][2] + bv0, acc[mt][nt][3] + bv1);
        }
    }
}

// ---------------------------------------------------------------------------
// Flash attention with TF32 tensor cores.
// Br=128 (8 warps x 16 rows, each warp full-width), Bc=32, Dh=64.
// Softmax row reductions stay within 4-lane shfl groups. P goes through smem
// transposed [kv][m] because tf32 C-frag layout != A-frag layout.
// ---------------------------------------------------------------------------
__global__ __launch_bounds__(256) void attn_tc(float* __restrict__ out)
{
    __shared__ float Ks[32][68];    // [kv][dh]
    __shared__ float Vs[32][68];    // [kv][dh]
    __shared__ float Ps[32][132];   // [kv][m]

    const int tid  = threadIdx.x;
    const int warp = tid >> 5;
    const int lane = tid & 31;
    const int g    = lane >> 2;
    const int t4   = lane & 3;
    const int bh   = blockIdx.y;
    const int qr0  = blockIdx.x * 128;

    const float* qp = g_q + (size_t)bh * SEQ * DHEAD;
    const float* kp = g_k + (size_t)bh * SEQ * DHEAD;
    const float* vp = g_v + (size_t)bh * SEQ * DHEAD;

    const float scale = 0.125f;   // 1/sqrt(64)

    // Preload Q fragments for this warp's 16 rows (scaled, tf32-rounded).
    const int r0 = qr0 + warp * 16 + g;
    unsigned qf[8][4];
    #pragma unroll
    for (int s = 0; s < 8; s++) {
        int kk = s * 8 + t4;
        qf[s][0] = __float_as_uint(f2tf32f(qp[(size_t)r0 * DHEAD + kk] * scale));
        qf[s][1] = __float_as_uint(f2tf32f(qp[(size_t)(r0 + 8) * DHEAD + kk] * scale));
        qf[s][2] = __float_as_uint(f2tf32f(qp[(size_t)r0 * DHEAD + kk + 4] * scale));
        qf[s][3] = __float_as_uint(f2tf32f(qp[(size_t)(r0 + 8) * DHEAD + kk + 4] * scale));
    }

    float m0v = -1e30f, m1v = -1e30f, l0 = 0.0f, l1 = 0.0f;
    float o[8][4] = {};

    // Prefetch first K/V tile into registers.
    // Tile = 32 kv rows x 64 dh = 512 float4; 256 threads x 2 float4 each.
    // idx in [0,512): kv = idx >> 4 (16 float4 per row), d4 = idx & 15.
    float4 kreg[2], vreg[2];
    #pragma unroll
    for (int it = 0; it < 2; it++) {
        int idx = tid + it * 256;
        int kv = idx >> 4, d4 = idx & 15;
        kreg[it] = *(const float4*)(kp + (size_t)kv * DHEAD + d4 * 4);
        vreg[it] = *(const float4*)(vp + (size_t)kv * DHEAD + d4 * 4);
    }

    const int ml = warp * 16 + g;   // local m (this lane's row within block)

    for (int kc = 0; kc < SEQ; kc += 32) {
        // Commit prefetched K/V tile to smem (tf32-rounded).
        #pragma unroll
        for (int it = 0; it < 2; it++) {
            int idx = tid + it * 256;
            int kv = idx >> 4, d4 = idx & 15;
            float4 kvv = kreg[it];
            Ks[kv][d4 * 4 + 0] = f2tf32f(kvv.x);
            Ks[kv][d4 * 4 + 1] = f2tf32f(kvv.y);
            Ks[kv][d4 * 4 + 2] = f2tf32f(kvv.z);
            Ks[kv][d4 * 4 + 3] = f2tf32f(kvv.w);
            float4 vvv = vreg[it];
            Vs[kv][d4 * 4 + 0] = f2tf32f(vvv.x);
            Vs[kv][d4 * 4 + 1] = f2tf32f(vvv.y);
            Vs[kv][d4 * 4 + 2] = f2tf32f(vvv.z);
            Vs[kv][d4 * 4 + 3] = f2tf32f(vvv.w);
        }
        __syncthreads();

        // Prefetch next tile.
        if (kc + 32 < SEQ) {
            #pragma unroll
            for (int it = 0; it < 2; it++) {
                int idx = tid + it * 256;
                int kv = idx >> 4, d4 = idx & 15;
                kreg[it] = *(const float4*)(kp + (size_t)(kc + 32 + kv) * DHEAD + d4 * 4);
                vreg[it] = *(const float4*)(vp + (size_t)(kc + 32 + kv) * DHEAD + d4 * 4);
            }
        }

        // S = Q K^T for this warp's 16 rows x 32 kv cols.
        float s_[4][4] = {};
        #pragma unroll
        for (int s8 = 0; s8 < 8; s8++) {
            #pragma unroll
            for (int nt = 0; nt < 4; nt++) {
                unsigned b0 = __float_as_uint(Ks[nt * 8 + g][s8 * 8 + t4]);
                unsigned b1 = __float_as_uint(Ks[nt * 8 + g][s8 * 8 + t4 + 4]);
                mma_tf32(s_[nt], qf[s8], b0, b1);
            }
        }

        // Online softmax. Row r0: regs 0,1 ; row r0+8: regs 2,3.
        float mx0 = -1e30f, mx1 = -1e30f;
        #pragma unroll
        for (int nt = 0; nt < 4; nt++) {
            mx0 = fmaxf(mx0, fmaxf(s_[nt][0], s_[nt][1]));
            mx1 = fmaxf(mx1, fmaxf(s_[nt][2], s_[nt][3]));
        }
        #pragma unroll
        for (int off = 1; off <= 2; off <<= 1) {
            mx0 = fmaxf(mx0, __shfl_xor_sync(0xffffffffu, mx0, off, 4));
            mx1 = fmaxf(mx1, __shfl_xor_sync(0xffffffffu, mx1, off, 4));
        }
        float mn0 = fmaxf(m0v, mx0);
        float mn1 = fmaxf(m1v, mx1);
        float alpha0 = __expf(m0v - mn0);
        float alpha1 = __expf(m1v - mn1);
        m0v = mn0; m1v = mn1;

        float rs0 = 0.0f, rs1 = 0.0f;
        #pragma unroll
        for (int nt = 0; nt < 4; nt++) {
            float p0 = __expf(s_[nt][0] - mn0);
            float p1 = __expf(s_[nt][1] - mn0);
            float p2 = __expf(s_[nt][2] - mn1);
            float p3 = __expf(s_[nt][3] - mn1);
            rs0 += p0 + p1; rs1 += p2 + p3;
            // Store P transposed [kv][m], tf32-rounded, for the PV mma.
            int kv = nt * 8 + 2 * t4;
            Ps[kv][ml]         = f2tf32f(p0);
            Ps[kv + 1][ml]     = f2tf32f(p1);
            Ps[kv][ml + 8]     = f2tf32f(p2);
            Ps[kv + 1][ml + 8] = f2tf32f(p3);
        }
        #pragma unroll
        for (int off = 1; off <= 2; off <<= 1) {
            rs0 += __shfl_xor_sync(0xffffffffu, rs0, off, 4);
            rs1 += __shfl_xor_sync(0xffffffffu, rs1, off, 4);
        }
        l0 = l0 * alpha0 + rs0;
        l1 = l1 * alpha1 + rs1;

        // Rescale running O.
        #pragma unroll
        for (int nt = 0; nt < 8; nt++) {
            o[nt][0] *= alpha0; o[nt][1] *= alpha0;
            o[nt][2] *= alpha1; o[nt][3] *= alpha1;
        }
        __syncwarp();

        // O += P V : k = 32 kv (4 ksteps), n = 64 dh (8 n-tiles).
        #pragma unroll
        for (int s4 = 0; s4 < 4; s4++) {
            unsigned a[4];
            int kk = s4 * 8 + t4;
            a[0] = __float_as_uint(Ps[kk][warp * 16 + g]);
            a[1] = __float_as_uint(Ps[kk][warp * 16 + g + 8]);
            a[2] = __float_as_uint(Ps[kk + 4][warp * 16 + g]);
            a[3] = __float_as_uint(Ps[kk + 4][warp * 16 + g + 8]);
            #pragma unroll
            for (int nt = 0; nt < 8; nt++) {
                unsigned b0 = __float_as_uint(Vs[kk][nt * 8 + g]);
                unsigned b1 = __float_as_uint(Vs[kk + 4][nt * 8 + g]);
                mma_tf32(o[nt], a, b0, b1);
            }
        }
        __syncthreads();   // protect Ks/Vs/Ps before next tile's stores
    }

    // Epilogue: normalize, write [B, N, D].
    const int b = bh >> 4;
    const int h = bh & 15;
    const float inv0 = 1.0f / l0;
    const float inv1 = 1.0f / l1;
    const int n0_ = qr0 + warp * 16 + g;
    #pragma unroll
    for (int nt = 0; nt < 8; nt++) {
        int d = nt * 8 + 2 * t4;
        float2 r0_ = make_float2(o[nt][0] * inv0, o[nt][1] * inv0);
        float2 r1_ = make_float2(o[nt][2] * inv1, o[nt][3] * inv1);
        *(float2*)(out + ((size_t)b * SEQ + n0_) * DIMM + h * DHEAD + d) = r0_;
        *(float2*)(out + ((size_t)b * SEQ + n0_ + 8) * DIMM + h * DHEAD + d) = r1_;
    }
}

// ---------------------------------------------------------------------------
extern "C" void kernel_launch(void* const* d_in, const int* in_sizes, int n_in,
                              void* d_out, int out_size)
{
    const float* x  = (const float*)d_in[0];
    const float* Wq = (const float*)d_in[1];
    const float* bq = (const float*)d_in[2];
    const float* Wk = (const float*)d_in[3];
    const float* bk = (const float*)d_in[4];
    const float* Wv = (const float*)d_in[5];
    const float* bv = (const float*)d_in[6];
    float* out = (float*)d_out;

    dim3 g1(DIMM / 128, (BATCH * SEQ) / 128, 3);   // (8, 64, 3)
    qkv_tc<<<g1, 256>>>(x, Wq, bq, Wk, bk, Wv, bv);

    dim3 g2(SEQ / 128, BHTOT);                     // (16, 64)
    attn_tc<<<g2, 256>>>(out);
}